// round 1
// baseline (speedup 1.0000x reference)
#include <cuda_runtime.h>

#define NQ 4
#define NL 3

// ---------- complex helpers (float2 = re, im) ----------
__device__ __forceinline__ float2 cmul(float2 a, float2 b) {
    return make_float2(fmaf(a.x, b.x, -a.y * b.y),
                       fmaf(a.x, b.y,  a.y * b.x));
}
// a*b + c
__device__ __forceinline__ float2 cfma(float2 a, float2 b, float2 c) {
    float2 r;
    r.x = fmaf(a.x, b.x, fmaf(-a.y, b.y, c.x));
    r.y = fmaf(a.x, b.y, fmaf( a.y, b.x, c.y));
    return r;
}

// ---------- gates on 16-amplitude register state ----------
// Index convention (matches jnp [B,2,2,2,2] flatten): wire q has stride 8>>q.

template<int M>
__device__ __forceinline__ void apply_rx(float2* s, float cc, float ss) {
    // U = [[c, -i s],[-i s, c]]
#pragma unroll
    for (int i = 0; i < 16; i++) {
        if (!(i & M)) {
            float2 a0 = s[i], a1 = s[i | M];
            s[i].x     = fmaf(cc, a0.x,  ss * a1.y);
            s[i].y     = fmaf(cc, a0.y, -ss * a1.x);
            s[i | M].x = fmaf(cc, a1.x,  ss * a0.y);
            s[i | M].y = fmaf(cc, a1.y, -ss * a0.x);
        }
    }
}

template<int M>
__device__ __forceinline__ void apply_u(float2* s, float2 u00, float2 u01,
                                        float2 u10, float2 u11) {
#pragma unroll
    for (int i = 0; i < 16; i++) {
        if (!(i & M)) {
            float2 a0 = s[i], a1 = s[i | M];
            s[i]     = cfma(u01, a1, cmul(u00, a0));
            s[i | M] = cfma(u11, a1, cmul(u10, a0));
        }
    }
}

template<int CM, int TM>
__device__ __forceinline__ void apply_cnot(float2* s) {
#pragma unroll
    for (int i = 0; i < 16; i++) {
        if ((i & CM) && !(i & TM)) {
            float2 t = s[i];
            s[i] = s[i | TM];
            s[i | TM] = t;
        }
    }
}

__global__ void __launch_bounds__(256)
qfe_kernel(const float* __restrict__ x, const float* __restrict__ w,
           float* __restrict__ out, int B)
{
    // Rot matrices shared across the whole batch: compute once per block.
    __shared__ float2 rot[NL][NQ][4];   // u00,u01,u10,u11
    const int tid = threadIdx.x;
    if (tid < NL * NQ) {
        const int layer = tid / NQ, q = tid % NQ;
        const float phi = w[(layer * NQ + q) * 3 + 0];
        const float th  = w[(layer * NQ + q) * 3 + 1];
        const float om  = w[(layer * NQ + q) * 3 + 2];
        float ct, st, sp, cp, sm, cm;
        sincosf(0.5f * th, &st, &ct);
        sincosf(0.5f * (phi + om), &sp, &cp);
        sincosf(0.5f * (phi - om), &sm, &cm);
        // Rot(phi,theta,omega) = RZ(om) RY(th) RZ(phi)
        rot[layer][q][0] = make_float2( cp * ct, -sp * ct);  // u00 = e^{-i(phi+om)/2} ct
        rot[layer][q][1] = make_float2(-cm * st, -sm * st);  // u01 = -e^{+i(phi-om)/2} st
        rot[layer][q][2] = make_float2( cm * st, -sm * st);  // u10 = e^{-i(phi-om)/2} st
        rot[layer][q][3] = make_float2( cp * ct,  sp * ct);  // u11 = e^{+i(phi+om)/2} ct
    }
    __syncthreads();

    const int b = blockIdx.x * blockDim.x + tid;
    if (b >= B) return;

    const float4 xv = reinterpret_cast<const float4*>(x)[b];
    float c[4], sn[4];
    __sincosf(0.5f * xv.x, &sn[0], &c[0]);
    __sincosf(0.5f * xv.y, &sn[1], &c[1]);
    __sincosf(0.5f * xv.z, &sn[2], &c[2]);
    __sincosf(0.5f * xv.w, &sn[3], &c[3]);

    // ---- Layer 0: state is a product state until the first CNOT ----
    // RX_q|0> = (c_q, -i s_q); then apply Rot per qubit on the 2-vector.
    float2 wv[4][2];
#pragma unroll
    for (int q = 0; q < 4; q++) {
        const float2 u00 = rot[0][q][0], u01 = rot[0][q][1];
        const float2 u10 = rot[0][q][2], u11 = rot[0][q][3];
        // v0=(c,0), v1=(0,-s):  u*v = u00*v0 + u01*v1 etc.
        wv[q][0] = make_float2(fmaf(u00.x, c[q],  u01.y * sn[q]),
                               fmaf(u00.y, c[q], -u01.x * sn[q]));
        wv[q][1] = make_float2(fmaf(u10.x, c[q],  u11.y * sn[q]),
                               fmaf(u10.y, c[q], -u11.x * sn[q]));
    }

    float2 s[16];
    {   // tensor product wv0 (x) wv1 (x) wv2 (x) wv3
        float2 t01[4];
#pragma unroll
        for (int i = 0; i < 4; i++)
            t01[i] = cmul(wv[0][i >> 1], wv[1][i & 1]);
        float2 t012[8];
#pragma unroll
        for (int i = 0; i < 8; i++)
            t012[i] = cmul(t01[i >> 1], wv[2][i & 1]);
#pragma unroll
        for (int i = 0; i < 16; i++)
            s[i] = cmul(t012[i >> 1], wv[3][i & 1]);
    }
    apply_cnot<8, 4>(s);
    apply_cnot<4, 2>(s);
    apply_cnot<2, 1>(s);

    // ---- Layers 1..2: full 16-amplitude evolution ----
#pragma unroll
    for (int layer = 1; layer < NL; layer++) {
        apply_rx<8>(s, c[0], sn[0]);
        apply_rx<4>(s, c[1], sn[1]);
        apply_rx<2>(s, c[2], sn[2]);
        apply_rx<1>(s, c[3], sn[3]);
#pragma unroll
        for (int q = 0; q < 4; q++) {
            const float2 u00 = rot[layer][q][0], u01 = rot[layer][q][1];
            const float2 u10 = rot[layer][q][2], u11 = rot[layer][q][3];
            if (q == 0) apply_u<8>(s, u00, u01, u10, u11);
            if (q == 1) apply_u<4>(s, u00, u01, u10, u11);
            if (q == 2) apply_u<2>(s, u00, u01, u10, u11);
            if (q == 3) apply_u<1>(s, u00, u01, u10, u11);
        }
        apply_cnot<8, 4>(s);
        apply_cnot<4, 2>(s);
        apply_cnot<2, 1>(s);
    }

    // ---- <Z_q> expectation values ----
    float z0 = 0.f, z1 = 0.f, z2 = 0.f, z3 = 0.f;
#pragma unroll
    for (int i = 0; i < 16; i++) {
        const float p = fmaf(s[i].x, s[i].x, s[i].y * s[i].y);
        z0 += (i & 8) ? -p : p;
        z1 += (i & 4) ? -p : p;
        z2 += (i & 2) ? -p : p;
        z3 += (i & 1) ? -p : p;
    }
    reinterpret_cast<float4*>(out)[b] = make_float4(z0, z1, z2, z3);
}

extern "C" void kernel_launch(void* const* d_in, const int* in_sizes, int n_in,
                              void* d_out, int out_size) {
    // Identify inputs by size: weights has 36 elements, x has B*4.
    const float* x = nullptr;
    const float* w = nullptr;
    int B = 0;
    for (int i = 0; i < n_in; i++) {
        if (in_sizes[i] == NL * NQ * 3) {
            w = (const float*)d_in[i];
        } else {
            x = (const float*)d_in[i];
            B = in_sizes[i] / NQ;
        }
    }
    float* out = (float*)d_out;
    const int threads = 256;
    const int blocks = (B + threads - 1) / threads;
    qfe_kernel<<<blocks, threads>>>(x, w, out, B);
}

// round 3
// speedup vs baseline: 1.1028x; 1.1028x over previous
#include <cuda_runtime.h>

#define NQ 4
#define NL 3
typedef unsigned long long u64;

// ---------- packed f32x2 helpers ----------
__device__ __forceinline__ u64 pk(float lo, float hi) {
    u64 r; asm("mov.b64 %0, {%1, %2};" : "=l"(r) : "f"(lo), "f"(hi)); return r;
}
__device__ __forceinline__ float2 upk(u64 a) {
    float lo, hi; asm("mov.b64 {%0, %1}, %2;" : "=f"(lo), "=f"(hi) : "l"(a));
    return make_float2(lo, hi);
}
__device__ __forceinline__ u64 f2mul(u64 a, u64 b) {
    u64 d; asm("mul.rn.f32x2 %0, %1, %2;" : "=l"(d) : "l"(a), "l"(b)); return d;
}
__device__ __forceinline__ u64 f2fma(u64 a, u64 b, u64 c) {
    u64 d; asm("fma.rn.f32x2 %0, %1, %2, %3;" : "=l"(d) : "l"(a), "l"(b), "l"(c)); return d;
}
__device__ __forceinline__ u64 swp(u64 a) {   // (x,y) -> (y,x): register-half swap (alu pipe)
    float2 t = upk(a); return pk(t.y, t.x);
}

// CNOT = compile-time register permutation (free after unroll)
template<int CM, int TM>
__device__ __forceinline__ void apply_cnot(u64* s) {
#pragma unroll
    for (int i = 0; i < 16; i++) {
        if ((i & CM) && !(i & TM)) { u64 t = s[i]; s[i] = s[i | TM]; s[i | TM] = t; }
    }
}

__global__ void __launch_bounds__(256)
qfe_kernel(const float* __restrict__ x, const float* __restrict__ w,
           float* __restrict__ out, int B)
{
    // Per (layer, qubit): merged gate is M = c*R + s*Q, with R = Rot and
    // Q = -i * (Rot @ X) batch-shared. Store R and Q in DUPLICATED packed form:
    //   [e][0] = (R_e.x,  R_e.x)   [e][1] = (-R_e.y, R_e.y)
    //   [e][2] = (Q_e.x,  Q_e.x)   [e][3] = (-Q_e.y, Q_e.y)
    // so M entries build & apply entirely with f32x2 FMA.
    __shared__ u64 gm[NL][NQ][4][4];      // entry e: 0=u00, 1=u01, 2=u10, 3=u11
    __shared__ float2 pl0[2][2];          // layer0 q0: plain [j][{R,Q}] for entries (j,0)

    const int tid = threadIdx.x;
    if (tid < NL * NQ) {
        const int layer = tid / NQ, q = tid % NQ;
        const float phi = w[(layer * NQ + q) * 3 + 0];
        const float th  = w[(layer * NQ + q) * 3 + 1];
        const float om  = w[(layer * NQ + q) * 3 + 2];
        float ct, st, sp, cp, sm, cm;
        sincosf(0.5f * th, &st, &ct);
        sincosf(0.5f * (phi + om), &sp, &cp);
        sincosf(0.5f * (phi - om), &sm, &cm);
        // Rot(phi,theta,omega) = RZ(om) RY(th) RZ(phi)
        float2 R[4];
        R[0] = make_float2( cp * ct, -sp * ct);   // u00
        R[1] = make_float2(-cm * st, -sm * st);   // u01
        R[2] = make_float2( cm * st, -sm * st);   // u10
        R[3] = make_float2( cp * ct,  sp * ct);   // u11
        // Q = -i * (R @ X): column swap then *(-i); -i*(x+iy) = (y, -x)
        float2 Q[4];
        Q[0] = make_float2(R[1].y, -R[1].x);
        Q[1] = make_float2(R[0].y, -R[0].x);
        Q[2] = make_float2(R[3].y, -R[3].x);
        Q[3] = make_float2(R[2].y, -R[2].x);
#pragma unroll
        for (int e = 0; e < 4; e++) {
            gm[layer][q][e][0] = pk( R[e].x, R[e].x);
            gm[layer][q][e][1] = pk(-R[e].y, R[e].y);
            gm[layer][q][e][2] = pk( Q[e].x, Q[e].x);
            gm[layer][q][e][3] = pk(-Q[e].y, Q[e].y);
        }
        if (layer == 0 && q == 0) {
            pl0[0][0] = R[0]; pl0[0][1] = Q[0];   // entry (0,0)
            pl0[1][0] = R[2]; pl0[1][1] = Q[2];   // entry (1,0)
        }
    }
    __syncthreads();

    const int b = blockIdx.x * blockDim.x + tid;
    if (b >= B) return;

    const float4 xv = reinterpret_cast<const float4*>(x)[b];
    float c_[4], s_[4];
    __sincosf(0.5f * xv.x, &s_[0], &c_[0]);
    __sincosf(0.5f * xv.y, &s_[1], &c_[1]);
    __sincosf(0.5f * xv.z, &s_[2], &c_[2]);
    __sincosf(0.5f * xv.w, &s_[3], &c_[3]);
    u64 cc[4], ss[4];
#pragma unroll
    for (int q = 0; q < 4; q++) { cc[q] = pk(c_[q], c_[q]); ss[q] = pk(s_[q], s_[q]); }

    // ---- Layer 0: product state = tensor of M_q|0> = column 0 of merged M_q ----
    // qubit 0 as plain complex; qubits 1..3 directly in duplicated form.
    u64 a0, a1;
    {
        float v0x = fmaf(c_[0], pl0[0][0].x, s_[0] * pl0[0][1].x);
        float v0y = fmaf(c_[0], pl0[0][0].y, s_[0] * pl0[0][1].y);
        float v1x = fmaf(c_[0], pl0[1][0].x, s_[0] * pl0[1][1].x);
        float v1y = fmaf(c_[0], pl0[1][0].y, s_[0] * pl0[1][1].y);
        a0 = pk(v0x, v0y); a1 = pk(v1x, v1y);
    }
    u64 wx[4][2], wy[4][2];
#pragma unroll
    for (int q = 1; q < 4; q++) {
#pragma unroll
        for (int j = 0; j < 2; j++) {
            const int e = j * 2;  // entries (0,0) and (1,0): e = 0, 2
            wx[q][j] = f2fma(ss[q], gm[0][q][e][2], f2mul(cc[q], gm[0][q][e][0]));
            wy[q][j] = f2fma(ss[q], gm[0][q][e][3], f2mul(cc[q], gm[0][q][e][1]));
        }
    }
    // tensor chain: cmul with dup-form right factor: w*a = wx.*a + wy.*swap(a)
    u64 t01[4];
    {
        const u64 sa0 = swp(a0), sa1 = swp(a1);
#pragma unroll
        for (int i = 0; i < 4; i++) {
            const u64 a  = (i & 2) ? a1 : a0;
            const u64 sa = (i & 2) ? sa1 : sa0;
            t01[i] = f2fma(wy[1][i & 1], sa, f2mul(wx[1][i & 1], a));
        }
    }
    u64 t012[8];
    {
        u64 st01[4];
#pragma unroll
        for (int i = 0; i < 4; i++) st01[i] = swp(t01[i]);
#pragma unroll
        for (int i = 0; i < 8; i++)
            t012[i] = f2fma(wy[2][i & 1], st01[i >> 1], f2mul(wx[2][i & 1], t01[i >> 1]));
    }
    u64 st[16];
    {
        u64 st012[8];
#pragma unroll
        for (int i = 0; i < 8; i++) st012[i] = swp(t012[i]);
#pragma unroll
        for (int i = 0; i < 16; i++)
            st[i] = f2fma(wy[3][i & 1], st012[i >> 1], f2mul(wx[3][i & 1], t012[i >> 1]));
    }
    apply_cnot<8, 4>(st);
    apply_cnot<4, 2>(st);
    apply_cnot<2, 1>(st);

    // ---- Layers 1..2: merged gate per qubit, fully packed ----
#pragma unroll
    for (int l = 1; l < NL; l++) {
#pragma unroll
        for (int q = 0; q < 4; q++) {
            const int M = 8 >> q;
            u64 ux[4], uy[4];
#pragma unroll
            for (int e = 0; e < 4; e++) {
                ux[e] = f2fma(ss[q], gm[l][q][e][2], f2mul(cc[q], gm[l][q][e][0]));
                uy[e] = f2fma(ss[q], gm[l][q][e][3], f2mul(cc[q], gm[l][q][e][1]));
            }
#pragma unroll
            for (int i = 0; i < 16; i++) {
                if (!(i & M)) {
                    const u64 b0 = st[i], b1 = st[i | M];
                    const u64 sb0 = swp(b0), sb1 = swp(b1);
                    st[i]     = f2fma(uy[1], sb1, f2fma(ux[1], b1,
                                 f2fma(uy[0], sb0, f2mul(ux[0], b0))));
                    st[i | M] = f2fma(uy[3], sb1, f2fma(ux[3], b1,
                                 f2fma(uy[2], sb0, f2mul(ux[2], b0))));
                }
            }
        }
        apply_cnot<8, 4>(st);
        apply_cnot<4, 2>(st);
        apply_cnot<2, 1>(st);
    }

    // ---- probabilities + <Z_q> via 2-level Walsh reduction ----
    float p[16];
#pragma unroll
    for (int i = 0; i < 16; i++) {
        const float2 t = upk(f2mul(st[i], st[i]));
        p[i] = t.x + t.y;
    }
    float e8[8], o8[8];
#pragma unroll
    for (int i = 0; i < 8; i++) { e8[i] = p[2*i] + p[2*i+1]; o8[i] = p[2*i] - p[2*i+1]; }
    float z3 = ((o8[0]+o8[1]) + (o8[2]+o8[3])) + ((o8[4]+o8[5]) + (o8[6]+o8[7]));
    float f4[4], g4[4];
#pragma unroll
    for (int j = 0; j < 4; j++) { f4[j] = e8[2*j] + e8[2*j+1]; g4[j] = e8[2*j] - e8[2*j+1]; }
    const float z2 = (g4[0] + g4[1]) + (g4[2] + g4[3]);
    const float z1 = (f4[0] - f4[1]) + (f4[2] - f4[3]);
    const float z0 = (f4[0] + f4[1]) - (f4[2] + f4[3]);

    reinterpret_cast<float4*>(out)[b] = make_float4(z0, z1, z2, z3);
}

extern "C" void kernel_launch(void* const* d_in, const int* in_sizes, int n_in,
                              void* d_out, int out_size) {
    const float* x = nullptr;
    const float* w = nullptr;
    int B = 0;
    for (int i = 0; i < n_in; i++) {
        if (in_sizes[i] == NL * NQ * 3) {
            w = (const float*)d_in[i];
        } else {
            x = (const float*)d_in[i];
            B = in_sizes[i] / NQ;
        }
    }
    float* out = (float*)d_out;
    const int threads = 256;
    const int blocks = (B + threads - 1) / threads;
    qfe_kernel<<<blocks, threads>>>(x, w, out, B);
}

// round 4
// speedup vs baseline: 1.1922x; 1.0811x over previous
#include <cuda_runtime.h>

#define NQ 4
#define NL 3

// ---------- complex helpers (float2 = re, im) ----------
__device__ __forceinline__ float2 cmul(float2 a, float2 b) {
    return make_float2(fmaf(a.x, b.x, -a.y * b.y),
                       fmaf(a.x, b.y,  a.y * b.x));
}
// a*b + c
__device__ __forceinline__ float2 cfma(float2 a, float2 b, float2 c) {
    float2 r;
    r.x = fmaf(a.x, b.x, fmaf(-a.y, b.y, c.x));
    r.y = fmaf(a.x, b.y, fmaf( a.y, b.x, c.y));
    return r;
}

template<int M>
__device__ __forceinline__ void apply_u(float2* s, float2 u00, float2 u01,
                                        float2 u10, float2 u11) {
#pragma unroll
    for (int i = 0; i < 16; i++) {
        if (!(i & M)) {
            float2 a0 = s[i], a1 = s[i | M];
            s[i]     = cfma(u01, a1, cmul(u00, a0));
            s[i | M] = cfma(u11, a1, cmul(u10, a0));
        }
    }
}

// CNOT = compile-time register permutation (free after unroll)
template<int CM, int TM>
__device__ __forceinline__ void apply_cnot(float2* s) {
#pragma unroll
    for (int i = 0; i < 16; i++) {
        if ((i & CM) && !(i & TM)) { float2 t = s[i]; s[i] = s[i | TM]; s[i | TM] = t; }
    }
}

__global__ void __launch_bounds__(256, 4)
qfe_kernel(const float* __restrict__ x, const float* __restrict__ w,
           float* __restrict__ out, int B)
{
    // Per (layer,qubit): merged gate M = c*R + s*Q with batch-shared
    // R = Rot(phi,th,om), Q = -i * (Rot @ X). Only c,s depend on the batch
    // element, so each thread builds M with 2 instrs/scalar and applies one
    // 2x2 complex gate per qubit-layer (the separate RX sweep is gone).
    __shared__ float2 gR[NL][NQ][4];   // entries: 0=u00, 1=u01, 2=u10, 3=u11
    __shared__ float2 gQ[NL][NQ][4];

    const int tid = threadIdx.x;
    if (tid < NL * NQ) {
        const int layer = tid / NQ, q = tid % NQ;
        const float phi = w[(layer * NQ + q) * 3 + 0];
        const float th  = w[(layer * NQ + q) * 3 + 1];
        const float om  = w[(layer * NQ + q) * 3 + 2];
        float ct, st, sp, cp, sm, cm;
        sincosf(0.5f * th, &st, &ct);
        sincosf(0.5f * (phi + om), &sp, &cp);
        sincosf(0.5f * (phi - om), &sm, &cm);
        // Rot(phi,theta,omega) = RZ(om) RY(th) RZ(phi)
        float2 R[4];
        R[0] = make_float2( cp * ct, -sp * ct);   // u00
        R[1] = make_float2(-cm * st, -sm * st);   // u01
        R[2] = make_float2( cm * st, -sm * st);   // u10
        R[3] = make_float2( cp * ct,  sp * ct);   // u11
        // Q = -i * (R @ X): column swap then *(-i);  -i*(x+iy) = (y, -x)
        float2 Q[4];
        Q[0] = make_float2(R[1].y, -R[1].x);
        Q[1] = make_float2(R[0].y, -R[0].x);
        Q[2] = make_float2(R[3].y, -R[3].x);
        Q[3] = make_float2(R[2].y, -R[2].x);
#pragma unroll
        for (int e = 0; e < 4; e++) { gR[layer][q][e] = R[e]; gQ[layer][q][e] = Q[e]; }
    }
    __syncthreads();

    const int b = blockIdx.x * blockDim.x + tid;
    if (b >= B) return;

    const float4 xv = reinterpret_cast<const float4*>(x)[b];
    float c_[4], s_[4];
    __sincosf(0.5f * xv.x, &s_[0], &c_[0]);
    __sincosf(0.5f * xv.y, &s_[1], &c_[1]);
    __sincosf(0.5f * xv.z, &s_[2], &c_[2]);
    __sincosf(0.5f * xv.w, &s_[3], &c_[3]);

    // ---- Layer 0: product state. M_q|0> = column 0 of merged gate ----
    float2 wv[4][2];
#pragma unroll
    for (int q = 0; q < 4; q++) {
#pragma unroll
        for (int j = 0; j < 2; j++) {
            const int e = j * 2;  // entries (0,0) and (1,0)
            wv[q][j].x = fmaf(s_[q], gQ[0][q][e].x, c_[q] * gR[0][q][e].x);
            wv[q][j].y = fmaf(s_[q], gQ[0][q][e].y, c_[q] * gR[0][q][e].y);
        }
    }
    float2 s[16];
    {   // tensor product wv0 (x) wv1 (x) wv2 (x) wv3
        float2 t01[4];
#pragma unroll
        for (int i = 0; i < 4; i++)
            t01[i] = cmul(wv[0][i >> 1], wv[1][i & 1]);
        float2 t012[8];
#pragma unroll
        for (int i = 0; i < 8; i++)
            t012[i] = cmul(t01[i >> 1], wv[2][i & 1]);
#pragma unroll
        for (int i = 0; i < 16; i++)
            s[i] = cmul(t012[i >> 1], wv[3][i & 1]);
    }
    apply_cnot<8, 4>(s);
    apply_cnot<4, 2>(s);
    apply_cnot<2, 1>(s);

    // ---- Layers 1..2: build merged M per qubit, apply once ----
#pragma unroll
    for (int l = 1; l < NL; l++) {
#pragma unroll
        for (int q = 0; q < 4; q++) {
            float2 m[4];
#pragma unroll
            for (int e = 0; e < 4; e++) {
                m[e].x = fmaf(s_[q], gQ[l][q][e].x, c_[q] * gR[l][q][e].x);
                m[e].y = fmaf(s_[q], gQ[l][q][e].y, c_[q] * gR[l][q][e].y);
            }
            if (q == 0) apply_u<8>(s, m[0], m[1], m[2], m[3]);
            if (q == 1) apply_u<4>(s, m[0], m[1], m[2], m[3]);
            if (q == 2) apply_u<2>(s, m[0], m[1], m[2], m[3]);
            if (q == 3) apply_u<1>(s, m[0], m[1], m[2], m[3]);
        }
        apply_cnot<8, 4>(s);
        apply_cnot<4, 2>(s);
        apply_cnot<2, 1>(s);
    }

    // ---- probabilities + <Z_q> via 2-level Walsh reduction ----
    float p[16];
#pragma unroll
    for (int i = 0; i < 16; i++)
        p[i] = fmaf(s[i].x, s[i].x, s[i].y * s[i].y);

    float e8[8], o8[8];
#pragma unroll
    for (int i = 0; i < 8; i++) { e8[i] = p[2*i] + p[2*i+1]; o8[i] = p[2*i] - p[2*i+1]; }
    const float z3 = ((o8[0]+o8[1]) + (o8[2]+o8[3])) + ((o8[4]+o8[5]) + (o8[6]+o8[7]));
    float f4[4], g4[4];
#pragma unroll
    for (int j = 0; j < 4; j++) { f4[j] = e8[2*j] + e8[2*j+1]; g4[j] = e8[2*j] - e8[2*j+1]; }
    const float z2 = (g4[0] + g4[1]) + (g4[2] + g4[3]);
    const float z1 = (f4[0] - f4[1]) + (f4[2] - f4[3]);
    const float z0 = (f4[0] + f4[1]) - (f4[2] + f4[3]);

    reinterpret_cast<float4*>(out)[b] = make_float4(z0, z1, z2, z3);
}

extern "C" void kernel_launch(void* const* d_in, const int* in_sizes, int n_in,
                              void* d_out, int out_size) {
    const float* x = nullptr;
    const float* w = nullptr;
    int B = 0;
    for (int i = 0; i < n_in; i++) {
        if (in_sizes[i] == NL * NQ * 3) {
            w = (const float*)d_in[i];
        } else {
            x = (const float*)d_in[i];
            B = in_sizes[i] / NQ;
        }
    }
    float* out = (float*)d_out;
    const int threads = 256;
    const int blocks = (B + threads - 1) / threads;
    qfe_kernel<<<blocks, threads>>>(x, w, out, B);
}

// round 5
// speedup vs baseline: 1.2008x; 1.0072x over previous
#include <cuda_runtime.h>

#define NQ 4
#define NL 3

// ---------- complex helpers (float2 = re, im) ----------
__device__ __forceinline__ float2 cmul(float2 a, float2 b) {
    return make_float2(fmaf(a.x, b.x, -a.y * b.y),
                       fmaf(a.x, b.y,  a.y * b.x));
}

// Apply SU(2) gate [[a, b], [-conj(b), conj(a)]] on the pairs split by mask M.
// All conjugations/negations fold into FFMA source sign modifiers (free).
template<int M>
__device__ __forceinline__ void apply_su2(float2* s, float2 a, float2 b) {
#pragma unroll
    for (int i = 0; i < 16; i++) {
        if (!(i & M)) {
            const float2 x0 = s[i], x1 = s[i | M];
            s[i].x     = fmaf(a.x, x0.x, fmaf(-a.y, x0.y, fmaf(b.x, x1.x, -b.y * x1.y)));
            s[i].y     = fmaf(a.x, x0.y, fmaf( a.y, x0.x, fmaf(b.x, x1.y,  b.y * x1.x)));
            s[i | M].x = fmaf(-b.x, x0.x, fmaf(-b.y, x0.y, fmaf(a.x, x1.x,  a.y * x1.y)));
            s[i | M].y = fmaf(-b.x, x0.y, fmaf( b.y, x0.x, fmaf(a.x, x1.y, -a.y * x1.x)));
        }
    }
}

// CNOT = compile-time permutation (free register renames after unroll)
template<int CM, int TM, typename T>
__device__ __forceinline__ void apply_cnot(T* s) {
#pragma unroll
    for (int i = 0; i < 16; i++) {
        if ((i & CM) && !(i & TM)) { T t = s[i]; s[i] = s[i | TM]; s[i | TM] = t; }
    }
}

// Merged gate M = Rot * RX(x) is SU(2): build its top row (a, b) from
// batch-shared Rot top row (R0, R1) and per-thread c = cos(x/2), s = sin(x/2).
// a = c*R0 + s*(R1.y, -R1.x) ;  b = c*R1 + s*(R0.y, -R0.x)
__device__ __forceinline__ void make_su2(float c, float s, float2 R0, float2 R1,
                                         float2& a, float2& b) {
    a.x = fmaf(s,  R1.y, c * R0.x);
    a.y = fmaf(-s, R1.x, c * R0.y);
    b.x = fmaf(s,  R0.y, c * R1.x);
    b.y = fmaf(-s, R0.x, c * R1.y);
}

__global__ void __launch_bounds__(256, 4)
qfe_kernel(const float* __restrict__ x, const float* __restrict__ w,
           float* __restrict__ out, int B)
{
    // Batch-shared Rot top row per (layer, qubit): [0] = u00, [1] = u01.
    // (Rot is SU(2): u10 = -conj(u01), u11 = conj(u00).)
    __shared__ float2 gr[NL][NQ][2];

    const int tid = threadIdx.x;
    if (tid < NL * NQ) {
        const int layer = tid / NQ, q = tid % NQ;
        const float phi = w[(layer * NQ + q) * 3 + 0];
        const float th  = w[(layer * NQ + q) * 3 + 1];
        const float om  = w[(layer * NQ + q) * 3 + 2];
        float ct, st, sp, cp, sm, cm;
        sincosf(0.5f * th, &st, &ct);
        sincosf(0.5f * (phi + om), &sp, &cp);
        sincosf(0.5f * (phi - om), &sm, &cm);
        // Rot(phi,theta,omega) = RZ(om) RY(th) RZ(phi)
        gr[layer][q][0] = make_float2( cp * ct, -sp * ct);   // u00
        gr[layer][q][1] = make_float2(-cm * st, -sm * st);   // u01
    }
    __syncthreads();

    const int b = blockIdx.x * blockDim.x + tid;
    if (b >= B) return;

    const float4 xv = reinterpret_cast<const float4*>(x)[b];
    float c_[4], s_[4];
    __sincosf(0.5f * xv.x, &s_[0], &c_[0]);
    __sincosf(0.5f * xv.y, &s_[1], &c_[1]);
    __sincosf(0.5f * xv.z, &s_[2], &c_[2]);
    __sincosf(0.5f * xv.w, &s_[3], &c_[3]);

    // ---- Layer 0: product state. M_q|0> = column 0 = (a, -conj(b)) ----
    float2 wv[4][2];
#pragma unroll
    for (int q = 0; q < 4; q++) {
        float2 a, bb;
        make_su2(c_[q], s_[q], gr[0][q][0], gr[0][q][1], a, bb);
        wv[q][0] = a;
        wv[q][1] = make_float2(-bb.x, bb.y);   // -conj(b); negs fold into cmul FMAs
    }
    float2 s[16];
    {   // balanced tensor product: (q0 (x) q1) (x) (q2 (x) q3)
        float2 t01[4], t23[4];
#pragma unroll
        for (int i = 0; i < 4; i++) {
            t01[i] = cmul(wv[0][i >> 1], wv[1][i & 1]);
            t23[i] = cmul(wv[2][i >> 1], wv[3][i & 1]);
        }
#pragma unroll
        for (int i = 0; i < 16; i++)
            s[i] = cmul(t01[i >> 2], t23[i & 3]);
    }
    apply_cnot<8, 4>(s);
    apply_cnot<4, 2>(s);
    apply_cnot<2, 1>(s);

    // ---- Layer 1: full 4-qubit sweep ----
    {
        float2 a, bb;
        make_su2(c_[0], s_[0], gr[1][0][0], gr[1][0][1], a, bb); apply_su2<8>(s, a, bb);
        make_su2(c_[1], s_[1], gr[1][1][0], gr[1][1][1], a, bb); apply_su2<4>(s, a, bb);
        make_su2(c_[2], s_[2], gr[1][2][0], gr[1][2][1], a, bb); apply_su2<2>(s, a, bb);
        make_su2(c_[3], s_[3], gr[1][3][0], gr[1][3][1], a, bb); apply_su2<1>(s, a, bb);
    }
    apply_cnot<8, 4>(s);
    apply_cnot<4, 2>(s);
    apply_cnot<2, 1>(s);

    // ---- Layer 2: q0..q2 normally; q3 fused into probabilities ----
    {
        float2 a, bb;
        make_su2(c_[0], s_[0], gr[2][0][0], gr[2][0][1], a, bb); apply_su2<8>(s, a, bb);
        make_su2(c_[1], s_[1], gr[2][1][0], gr[2][1][1], a, bb); apply_su2<4>(s, a, bb);
        make_su2(c_[2], s_[2], gr[2][2][0], gr[2][2][1], a, bb); apply_su2<2>(s, a, bb);
    }
    // q3 gate + |.|^2 with unitarity: p_hi = (|x0|^2 + |x1|^2) - p_lo
    float p[16];
    {
        float2 a, bb;
        make_su2(c_[3], s_[3], gr[2][3][0], gr[2][3][1], a, bb);
#pragma unroll
        for (int i = 0; i < 16; i += 2) {
            const float2 x0 = s[i], x1 = s[i | 1];
            const float y0x = fmaf(a.x, x0.x, fmaf(-a.y, x0.y, fmaf(bb.x, x1.x, -bb.y * x1.y)));
            const float y0y = fmaf(a.x, x0.y, fmaf( a.y, x0.x, fmaf(bb.x, x1.y,  bb.y * x1.x)));
            const float n   = fmaf(x0.x, x0.x, fmaf(x0.y, x0.y,
                              fmaf(x1.x, x1.x, x1.y * x1.y)));
            const float plo = fmaf(y0x, y0x, y0y * y0y);
            p[i]     = plo;
            p[i | 1] = n - plo;
        }
    }
    // final CNOT chain permutes basis states -> permute probabilities (free)
    apply_cnot<8, 4>(p);
    apply_cnot<4, 2>(p);
    apply_cnot<2, 1>(p);

    // ---- <Z_q> via 2-level Walsh reduction ----
    float e8[8], o8[8];
#pragma unroll
    for (int i = 0; i < 8; i++) { e8[i] = p[2*i] + p[2*i+1]; o8[i] = p[2*i] - p[2*i+1]; }
    const float z3 = ((o8[0]+o8[1]) + (o8[2]+o8[3])) + ((o8[4]+o8[5]) + (o8[6]+o8[7]));
    float f4[4], g4[4];
#pragma unroll
    for (int j = 0; j < 4; j++) { f4[j] = e8[2*j] + e8[2*j+1]; g4[j] = e8[2*j] - e8[2*j+1]; }
    const float z2 = (g4[0] + g4[1]) + (g4[2] + g4[3]);
    const float z1 = (f4[0] - f4[1]) + (f4[2] - f4[3]);
    const float z0 = (f4[0] + f4[1]) - (f4[2] + f4[3]);

    reinterpret_cast<float4*>(out)[b] = make_float4(z0, z1, z2, z3);
}

extern "C" void kernel_launch(void* const* d_in, const int* in_sizes, int n_in,
                              void* d_out, int out_size) {
    const float* x = nullptr;
    const float* w = nullptr;
    int B = 0;
    for (int i = 0; i < n_in; i++) {
        if (in_sizes[i] == NL * NQ * 3) {
            w = (const float*)d_in[i];
        } else {
            x = (const float*)d_in[i];
            B = in_sizes[i] / NQ;
        }
    }
    float* out = (float*)d_out;
    const int threads = 256;
    const int blocks = (B + threads - 1) / threads;
    qfe_kernel<<<blocks, threads>>>(x, w, out, B);
}